// round 17
// baseline (speedup 1.0000x reference)
#include <cuda_runtime.h>
#include <cstdint>

// ---------------------------------------------------------------------------
// RipsECC. B=4096 points in [0,1]^3, 64 bins, bin(d) = ceil(31.5*d) in [0,55].
// All C(4096,2)=8,386,560 pairs are edges. out = cumsum(+4096 at bin0 - hist).
//
// R15 chassis + f32x2 PACKED MATH (2 pairs per FMA, PTX-only on sm_103a):
//  * j-points staged PRE-DUPLICATED: dupA[j]=(X,X,Y,Y), dupB[j]=(Z,Z,W,W),
//    prescaled x31.5, W = X^2+Y^2+Z^2. 128 KB smem; loads feed fma.rn.f32x2
//    directly (no per-j duplication MOVs).
//  * per i-pair (i0,i1): m01 = A01*xx + B01*yy + C01*zz + (K01 + ww), all
//    lanewise on f32x2 -> 4 packed ops replace 8 scalar ops.
//  * bin: MUFU.SQRT per scalar + F2I.RU (NaN -> 0; t in [0,55], bounded).
//  * u8 histogram 64KB: [8 regions][64 bins][32 lanes] words; warp quad
//    shares a word, byte bank = warp&3 (race-free; <=64 counts/slot).
//    Zeroed IN FULL (4 x STS.128 per thread).
//  * units: per 128-row superblock s, 8 diagonal 16-j chunks (predicated) +
//    (248-8s) off-diag 16-j chunks; prefix(s) = 4s(65-s); NUNITS=4224/4736.
//  * tail: proven per-block g_part matrix + ticket + last-block scan.
// ---------------------------------------------------------------------------

#define NPTS      4096
#define NSTEPS    64
#define NTHREADS  1024
#define NBLOCKS   148
#define NUNITS    4224
#define NREGIONS  8
#define HIST_WORDS (NREGIONS * NSTEPS * 32)         // 16384 words = 64 KB
#define DUP_FLOATS (8 * NPTS)                       // dupA+dupB = 128 KB
#define SMEM_BYTES (DUP_FLOATS * 4 + HIST_WORDS * 4)  // 196608 B

__device__ int      g_part[NBLOCKS][NSTEPS];
__device__ unsigned g_ticket = 0;

extern __shared__ float smemf[];

__device__ __forceinline__ unsigned long long pack2(float lo, float hi) {
    unsigned long long r;
    asm("mov.b64 %0, {%1, %2};" : "=l"(r) : "f"(lo), "f"(hi));
    return r;
}

// Two pairs at once: m01 = A*xx + B*yy + C*zz + (K + ww), lanewise f32x2;
// then scalar MUFU.SQRT + F2I.RU per lane (F2I(NaN)=0 keeps t bounded).
__device__ __forceinline__ void bin2(
    unsigned long long A, unsigned long long B, unsigned long long C,
    unsigned long long K, unsigned long long xx, unsigned long long yy,
    unsigned long long zz, unsigned long long ww, int& t0, int& t1) {
    unsigned long long acc;
    asm("add.rn.f32x2 %0, %1, %2;" : "=l"(acc) : "l"(K), "l"(ww));
    asm("fma.rn.f32x2 %0, %1, %2, %3;" : "=l"(acc) : "l"(C), "l"(zz), "l"(acc));
    asm("fma.rn.f32x2 %0, %1, %2, %3;" : "=l"(acc) : "l"(B), "l"(yy), "l"(acc));
    asm("fma.rn.f32x2 %0, %1, %2, %3;" : "=l"(acc) : "l"(A), "l"(xx), "l"(acc));
    float m0, m1;
    asm("mov.b64 {%0, %1}, %2;" : "=f"(m0), "=f"(m1) : "l"(acc));
    float d0, d1;
    asm("sqrt.approx.f32 %0, %1;" : "=f"(d0) : "f"(m0));   // MUFU.SQRT
    asm("sqrt.approx.f32 %0, %1;" : "=f"(d1) : "f"(m1));
    t0 = __float2int_ru(d0);
    t1 = __float2int_ru(d1);
}

__global__ void __launch_bounds__(NTHREADS, 1)
rips_ecc_kernel(const float* __restrict__ x, float* __restrict__ out) {
    float4*        dupA = (float4*)smemf;               // [4096] (X,X,Y,Y)
    float4*        dupB = (float4*)(smemf + 4 * NPTS);  // [4096] (Z,Z,W,W)
    unsigned*      hist = (unsigned*)(smemf + DUP_FLOATS);  // [8][64][32]
    unsigned char* h8   = (unsigned char*)hist;

    const int tid = threadIdx.x;

    // Stage 4 points per thread from 3 LDG.128, prescaled x31.5, duplicated.
    {
        const float4* xv = (const float4*)x;            // 3072 float4
        float4 v0 = xv[3 * tid + 0];
        float4 v1 = xv[3 * tid + 1];
        float4 v2 = xv[3 * tid + 2];
        float c[12] = {v0.x, v0.y, v0.z, v0.w, v1.x, v1.y,
                       v1.z, v1.w, v2.x, v2.y, v2.z, v2.w};
        #pragma unroll
        for (int h = 0; h < 4; h++) {
            float px = 31.5f * c[3 * h + 0];
            float py = 31.5f * c[3 * h + 1];
            float pz = 31.5f * c[3 * h + 2];
            float w  = fmaf(px, px, fmaf(py, py, pz * pz));
            dupA[4 * tid + h] = make_float4(px, px, py, py);
            dupB[4 * tid + h] = make_float4(pz, pz, w, w);
        }
    }
    // Zero the FULL 64KB histogram: 4096 uint4 = 4 x STS.128 per thread.
    {
        uint4* h4 = (uint4*)hist;
        #pragma unroll
        for (int i = 0; i < HIST_WORDS / 4 / NTHREADS; i++)   // 4 iterations
            h4[i * NTHREADS + tid] = make_uint4(0u, 0u, 0u, 0u);
    }
    __syncthreads();

    const int warp = tid >> 5;   // 0..31
    const int lane = tid & 31;
    // u8 slot: region = warp>>2 (8192 B each), byte = lane*4 + (warp&3).
    unsigned char* myh = h8 + (warp >> 2) * 8192 + lane * 4 + (warp & 3);

    const int u = warp * NBLOCKS + blockIdx.x;          // [0, 4736)
    if (u < NUNITS) {
        // prefix(s) = 4s(65-s); s = (65 - sqrt(4225-u))/2, fixup (proven).
        int s = (int)(0.5f * (65.0f - sqrtf((float)(4225 - u))));
        s = max(0, min(31, s));
        while (s > 0  && 4 * s * (65 - s) > u) --s;
        while (s < 31 && 4 * (s + 1) * (64 - s) <= u) ++s;
        const int rem   = u - 4 * s * (65 - s);         // [0, 8*(32-s))
        const int sbase = s << 7;

        // Per-unit constants: A/B/C = -2*coord, K = |P|^2, packed pairwise.
        float4 f0 = dupA[sbase + lane],      g0 = dupB[sbase + lane];
        float4 f1 = dupA[sbase + 32 + lane], g1 = dupB[sbase + 32 + lane];
        float4 f2 = dupA[sbase + 64 + lane], g2 = dupB[sbase + 64 + lane];
        float4 f3 = dupA[sbase + 96 + lane], g3 = dupB[sbase + 96 + lane];
        const unsigned long long A01 = pack2(-2.0f * f0.x, -2.0f * f1.x);
        const unsigned long long B01 = pack2(-2.0f * f0.z, -2.0f * f1.z);
        const unsigned long long C01 = pack2(-2.0f * g0.x, -2.0f * g1.x);
        const unsigned long long K01 = pack2(g0.z, g1.z);
        const unsigned long long A23 = pack2(-2.0f * f2.x, -2.0f * f3.x);
        const unsigned long long B23 = pack2(-2.0f * f2.z, -2.0f * f3.z);
        const unsigned long long C23 = pack2(-2.0f * g2.x, -2.0f * g3.x);
        const unsigned long long K23 = pack2(g2.z, g3.z);

        const ulonglong2* dA = (const ulonglong2*)dupA;  // (xx, yy)
        const ulonglong2* dB = (const ulonglong2*)dupB;  // (zz, ww)

        if (rem < 8) {
            // Diagonal chunk: jrel = 16*rem + jj; count (i_q, j) iff
            // jrel > 32q + lane.
            const int jr0 = rem << 4;
            #pragma unroll
            for (int jj = 0; jj < 16; jj++) {
                int jrel = jr0 + jj;
                ulonglong2 ua = dA[sbase + jrel];
                ulonglong2 ub = dB[sbase + jrel];
                int t0, t1, t2, t3;
                bin2(A01, B01, C01, K01, ua.x, ua.y, ub.x, ub.y, t0, t1);
                bin2(A23, B23, C23, K23, ua.x, ua.y, ub.x, ub.y, t2, t3);
                if (jrel > lane)      myh[t0 << 7] += (unsigned char)1;
                if (jrel > lane + 32) myh[t1 << 7] += (unsigned char)1;
                if (jrel > lane + 64) myh[t2 << 7] += (unsigned char)1;
                if (jrel > lane + 96) myh[t3 << 7] += (unsigned char)1;
            }
        } else {
            // Off-diagonal chunk: 16 j's past the superblock.
            const int j0 = sbase + 128 + ((rem - 8) << 4);
            #pragma unroll
            for (int jj = 0; jj < 16; jj++) {
                ulonglong2 ua = dA[j0 + jj];
                ulonglong2 ub = dB[j0 + jj];
                int t0, t1, t2, t3;
                bin2(A01, B01, C01, K01, ua.x, ua.y, ub.x, ub.y, t0, t1);
                bin2(A23, B23, C23, K23, ua.x, ua.y, ub.x, ub.y, t2, t3);
                myh[t0 << 7] += (unsigned char)1;
                myh[t1 << 7] += (unsigned char)1;
                myh[t2 << 7] += (unsigned char)1;
                myh[t3 << 7] += (unsigned char)1;
            }
        }
    }
    __syncthreads();

    // Block reduction: warp w reduces bins {2w, 2w+1}; dp4a sums the 4
    // byte-banks per word across 8 regions; write per-block partials.
    #pragma unroll
    for (int bb = 0; bb < 2; bb++) {
        int bin = warp * 2 + bb;
        int sa = 0;
        #pragma unroll
        for (int r = 0; r < NREGIONS; r++)
            sa = __dp4a((int)hist[r * 2048 + (bin << 5) + lane], 0x01010101, sa);
        #pragma unroll
        for (int o = 16; o > 0; o >>= 1)
            sa += __shfl_down_sync(0xffffffffu, sa, o);
        if (lane == 0)
            g_part[blockIdx.x][bin] = sa;
    }
    __threadfence();
    __syncthreads();

    __shared__ int s_last;
    if (tid == 0)
        s_last = (atomicAdd(&g_ticket, 1u) == NBLOCKS - 1);
    __syncthreads();
    if (!s_last) return;
    __threadfence();

    // --- last block: reduce 148x64 partials, cumsum, write, reset ticket ---
    __shared__ int red[NSTEPS * 16];
    {
        int bin = tid & 63;
        int grp = tid >> 6;               // 0..15
        int sa = 0;
        for (int b2 = grp; b2 < NBLOCKS; b2 += 16)
            sa += g_part[b2][bin];
        red[bin * 16 + grp] = sa;
    }
    __syncthreads();
    __shared__ int ecc[NSTEPS];
    if (tid < NSTEPS) {
        int tot = 0;
        #pragma unroll
        for (int g = 0; g < 16; g++) tot += red[tid * 16 + g];
        ecc[tid] = (tid == 0 ? NPTS : 0) - tot;
    }
    __syncthreads();
    if (tid < 32) {
        int e0 = ecc[tid];
        int e1 = ecc[tid + 32];
        #pragma unroll
        for (int d = 1; d < 32; d <<= 1) {
            int t = __shfl_up_sync(0xffffffffu, e0, d);
            if (tid >= d) e0 += t;
        }
        int tot = __shfl_sync(0xffffffffu, e0, 31);
        #pragma unroll
        for (int d = 1; d < 32; d <<= 1) {
            int t = __shfl_up_sync(0xffffffffu, e1, d);
            if (tid >= d) e1 += t;
        }
        e1 += tot;
        out[tid]      = (float)e0;
        out[tid + 32] = (float)e1;
    }
    if (tid == 0) g_ticket = 0;   // self-reset for graph replay
}

extern "C" void kernel_launch(void* const* d_in, const int* in_sizes, int n_in,
                              void* d_out, int out_size) {
    (void)in_sizes; (void)n_in; (void)out_size;
    const float* x = (const float*)d_in[0];
    float* out = (float*)d_out;

    cudaFuncSetAttribute(rips_ecc_kernel,
                         cudaFuncAttributeMaxDynamicSharedMemorySize, SMEM_BYTES);

    rips_ecc_kernel<<<NBLOCKS, NTHREADS, SMEM_BYTES>>>(x, out);
}